// round 16
// baseline (speedup 1.0000x reference)
#include <cuda_runtime.h>
#include <cuda_bf16.h>
#include <cstdint>

// Problem constants
#define D        64
#define S        64
#define BSZ      512
#define LTW      2016          // d*(d-1)/2
#define ZROW     6112          // lt + d*d
#define OUT_ELEMS (BSZ * S * D) // 2097152, z_adj follows at this offset

// ---------------- helpers ----------------
__device__ __forceinline__ uint32_t pack_h(unsigned short lo, unsigned short hi) {
    return (uint32_t)lo | ((uint32_t)hi << 16);
}
__device__ __forceinline__ void bsplit(float v, unsigned short& h, unsigned short& l) {
    __nv_bfloat16 bh = __float2bfloat16(v);
    float r = v - __bfloat162float(bh);
    __nv_bfloat16 bl = __float2bfloat16(r);
    h = *(unsigned short*)&bh;
    l = *(unsigned short*)&bl;
}

// mma.sync m16n8k16 row.col bf16 -> f32 accumulate (in-place on d)
__device__ __forceinline__ void mma16816(float* d, const uint32_t* a, uint32_t b0, uint32_t b1) {
    asm volatile(
        "mma.sync.aligned.m16n8k16.row.col.f32.bf16.bf16.f32 "
        "{%0,%1,%2,%3}, {%4,%5,%6,%7}, {%8,%9}, {%0,%1,%2,%3};"
        : "+f"(d[0]), "+f"(d[1]), "+f"(d[2]), "+f"(d[3])
        : "r"(a[0]), "r"(a[1]), "r"(a[2]), "r"(a[3]), "r"(b0), "r"(b1));
}

// x fragments: [w][mt][kt][lane][8 words]   words: a0h,a1h,a2h,a3h, a0l,a1l,a2l,a3l
__device__ uint32_t xfrag[4 * 8 * 4 * 32 * 8];

// ---------------- Kernel A: z_adj[s] = z_p^T @ z_lt @ z_p ----------------
__global__ void zadj_kernel(const float* __restrict__ z, float* __restrict__ adj_out) {
    extern __shared__ float sm[];
    float* lt  = sm;
    float* p   = sm + 4096;
    float* tmp = sm + 8192;
    const int s   = blockIdx.x;
    const int tid = threadIdx.x;
    const int nt  = blockDim.x;
    const float* zs = z + s * ZROW;

    for (int e = tid; e < 4096; e += nt) { lt[e] = 0.0f; p[e] = zs[LTW + e]; }
    __syncthreads();

    for (int k = tid; k < LTW; k += nt) {
        int i = (int)((sqrtf(8.0f * (float)k + 1.0f) + 1.0f) * 0.5f);
        while (i * (i - 1) / 2 > k)  --i;
        while ((i + 1) * i / 2 <= k) ++i;
        int j = k - i * (i - 1) / 2;
        lt[i * 64 + j] = zs[k];
    }
    __syncthreads();

    for (int e = tid; e < 4096; e += nt) {
        int r = e >> 6, j = e & 63;
        float acc = 0.0f;
        for (int t = 0; t < r; ++t) acc += lt[r * 64 + t] * p[t * 64 + j];
        tmp[e] = acc;
    }
    __syncthreads();

    for (int e = tid; e < 4096; e += nt) {
        int i = e >> 6, j = e & 63;
        float acc = 0.0f;
        #pragma unroll 8
        for (int r = 0; r < 64; ++r) acc += p[r * 64 + i] * tmp[r * 64 + j];
        adj_out[s * 4096 + e] = acc;
    }
}

// ---------------- Kernel A2: build xfrag (hi/lo split, fragment layout) ----------------
__global__ void xprep_kernel(const float* __restrict__ x) {
    int id = blockIdx.x * 256 + threadIdx.x;   // 0..16383 : (w,mt,kt,t,ai)
    int ai = id & 3;
    int t  = (id >> 2) & 31;
    int kt = (id >> 7) & 3;
    int mt = (id >> 9) & 7;
    int w  = id >> 12;
    int q  = t & 3;
    int r  = (t >> 2) + (ai & 1) * 8;
    int brow = w * 128 + mt * 16 + r;
    int cb = kt * 16 + 2 * q + ((ai >> 1) ? 8 : 0);
    float v0 = x[brow * 64 + cb];
    float v1 = x[brow * 64 + cb + 1];
    unsigned short h0, l0, h1, l1;
    bsplit(v0, h0, l0);
    bsplit(v1, h1, l1);
    uint32_t base = (uint32_t)((((w * 8 + mt) * 4 + kt) * 32 + t) * 8);
    xfrag[base + ai]     = pack_h(h0, h1);
    xfrag[base + 4 + ai] = pack_h(l0, l1);
}

// ---------------- Kernel B: HMMA fused MLP ----------------
// Grid (c, s) = 64x64; 128 threads = 4 warps, warp w handles batches [w*128, w*128+128).
// Per-lane weight fragments pre-cooked in shared: uint4 {b0h, b0l, b1h, b1l}.
__global__ void __launch_bounds__(128, 4) mlp_mma_kernel(
    const float* __restrict__ adj,
    const float* __restrict__ W0, const float* __restrict__ b0,
    const float* __restrict__ W1, const float* __restrict__ b1,
    const float* __restrict__ W2, const float* __restrict__ b2,
    const float* __restrict__ W3, const float* __restrict__ b3,
    float* __restrict__ out)
{
    __shared__ __align__(16) uint4 bf0[4][4][32];   // [nt][kt][lane]  8KB
    __shared__ __align__(16) uint4 bf1[4][2][32];   // 4KB
    __shared__ __align__(16) uint4 bf2[4][2][32];   // 4KB
    __shared__ float bias0[32], bias1[32], bias2[32], w3s[32], b3s;
    __shared__ float zcs[64];

    const int c = blockIdx.x, s = blockIdx.y;
    const int tid = threadIdx.x;
    const int wid = tid >> 5, lane = tid & 31;
    const int q = lane & 3, nrow = lane >> 2;

    // ---- stage scalars ----
    if (tid < 64) zcs[tid] = adj[s * 4096 + tid * 64 + c];
    if (tid < 32) {
        bias0[tid] = b0[c * 32 + tid];
        bias1[tid] = b1[c * 32 + tid];
        bias2[tid] = b2[c * 32 + tid];
        w3s[tid]   = W3[c * 32 + tid];
    }
    if (tid == 0) b3s = b3[c];
    __syncthreads();

    // ---- stage layer-0 weight fragments (W0 * zc, hi/lo split) ----
    // item e in [0,512): nt = e>>7, kt = (e>>5)&3, t = e&31
    #pragma unroll
    for (int it = 0; it < 4; ++it) {
        int e = tid + it * 128;
        int fnt = e >> 7, fkt = (e >> 5) & 3, ft = e & 31;
        int fq = ft & 3;
        int n = fnt * 8 + (ft >> 2);
        int k0 = fkt * 16 + 2 * fq;
        const float* wr = W0 + c * 2048 + n * 64;
        float v00 = wr[k0]     * zcs[k0];
        float v01 = wr[k0 + 1] * zcs[k0 + 1];
        float v10 = wr[k0 + 8] * zcs[k0 + 8];
        float v11 = wr[k0 + 9] * zcs[k0 + 9];
        unsigned short h, l, h2, l2;
        uint4 r;
        bsplit(v00, h, l); bsplit(v01, h2, l2);
        r.x = pack_h(h, h2); r.y = pack_h(l, l2);
        bsplit(v10, h, l); bsplit(v11, h2, l2);
        r.z = pack_h(h, h2); r.w = pack_h(l, l2);
        bf0[fnt][fkt][ft] = r;
    }
    // ---- stage layer-1/2 fragments: items e in [0,256) each ----
    #pragma unroll
    for (int it = 0; it < 2; ++it) {
        int e = tid + it * 128;
        int fnt = e >> 6, fkt = (e >> 5) & 1, ft = e & 31;
        int fq = ft & 3;
        int n = fnt * 8 + (ft >> 2);
        int k0 = fkt * 16 + 2 * fq;
        {
            const float* wr = W1 + c * 1024 + n * 32;
            unsigned short h, l, h2, l2;
            uint4 r;
            bsplit(wr[k0], h, l); bsplit(wr[k0 + 1], h2, l2);
            r.x = pack_h(h, h2); r.y = pack_h(l, l2);
            bsplit(wr[k0 + 8], h, l); bsplit(wr[k0 + 9], h2, l2);
            r.z = pack_h(h, h2); r.w = pack_h(l, l2);
            bf1[fnt][fkt][ft] = r;
        }
        {
            const float* wr = W2 + c * 1024 + n * 32;
            unsigned short h, l, h2, l2;
            uint4 r;
            bsplit(wr[k0], h, l); bsplit(wr[k0 + 1], h2, l2);
            r.x = pack_h(h, h2); r.y = pack_h(l, l2);
            bsplit(wr[k0 + 8], h, l); bsplit(wr[k0 + 9], h2, l2);
            r.z = pack_h(h, h2); r.w = pack_h(l, l2);
            bf2[fnt][fkt][ft] = r;
        }
    }
    __syncthreads();

    // per-thread bias pairs (col = nt*8 + 2q + {0,1})
    float bi0[4][2], bi1[4][2], bi2[4][2], w3v[4][2];
    #pragma unroll
    for (int nt = 0; nt < 4; ++nt) {
        int col = nt * 8 + 2 * q;
        bi0[nt][0] = bias0[col]; bi0[nt][1] = bias0[col + 1];
        bi1[nt][0] = bias1[col]; bi1[nt][1] = bias1[col + 1];
        bi2[nt][0] = bias2[col]; bi2[nt][1] = bias2[col + 1];
        w3v[nt][0] = w3s[col];   w3v[nt][1] = w3s[col + 1];
    }

    const int base_out = s * 64 + c;

    #pragma unroll 1
    for (int mt = 0; mt < 8; ++mt) {
        // ---- load A0 fragments (hi & lo) ----
        uint32_t aH[4][4], aL[4][4];
        #pragma unroll
        for (int kt = 0; kt < 4; ++kt) {
            const uint4* src = (const uint4*)(xfrag + (((wid * 8 + mt) * 4 + kt) * 32 + lane) * 8);
            uint4 vh = src[0], vl = src[1];
            aH[kt][0] = vh.x; aH[kt][1] = vh.y; aH[kt][2] = vh.z; aH[kt][3] = vh.w;
            aL[kt][0] = vl.x; aL[kt][1] = vl.y; aL[kt][2] = vl.z; aL[kt][3] = vl.w;
        }

        // ---- layer 0: K=64, 4 nt, 12 mma each ----
        uint32_t nAh[2][4], nAl[2][4];
        #pragma unroll
        for (int nt = 0; nt < 4; ++nt) {
            float dd[4] = { bi0[nt][0], bi0[nt][1], bi0[nt][0], bi0[nt][1] };
            #pragma unroll
            for (int kt = 0; kt < 4; ++kt) {
                uint4 B = bf0[nt][kt][lane];
                mma16816(dd, aH[kt], B.x, B.z);   // hi*hi
                mma16816(dd, aH[kt], B.y, B.w);   // hi*lo
                mma16816(dd, aL[kt], B.x, B.z);   // lo*hi
            }
            // relu + split -> next-layer A fragments (in-register)
            unsigned short h0, l0, h1, l1, h2, l2, h3, l3;
            bsplit(fmaxf(dd[0], 0.0f), h0, l0);
            bsplit(fmaxf(dd[1], 0.0f), h1, l1);
            bsplit(fmaxf(dd[2], 0.0f), h2, l2);
            bsplit(fmaxf(dd[3], 0.0f), h3, l3);
            int kt2 = nt >> 1, half = (nt & 1) * 2;
            nAh[kt2][half]     = pack_h(h0, h1);
            nAh[kt2][half + 1] = pack_h(h2, h3);
            nAl[kt2][half]     = pack_h(l0, l1);
            nAl[kt2][half + 1] = pack_h(l2, l3);
        }

        // ---- layer 1: K=32 ----
        uint32_t mAh[2][4], mAl[2][4];
        #pragma unroll
        for (int nt = 0; nt < 4; ++nt) {
            float dd[4] = { bi1[nt][0], bi1[nt][1], bi1[nt][0], bi1[nt][1] };
            #pragma unroll
            for (int kt = 0; kt < 2; ++kt) {
                uint4 B = bf1[nt][kt][lane];
                mma16816(dd, nAh[kt], B.x, B.z);
                mma16816(dd, nAh[kt], B.y, B.w);
                mma16816(dd, nAl[kt], B.x, B.z);
            }
            unsigned short h0, l0, h1, l1, h2, l2, h3, l3;
            bsplit(fmaxf(dd[0], 0.0f), h0, l0);
            bsplit(fmaxf(dd[1], 0.0f), h1, l1);
            bsplit(fmaxf(dd[2], 0.0f), h2, l2);
            bsplit(fmaxf(dd[3], 0.0f), h3, l3);
            int kt2 = nt >> 1, half = (nt & 1) * 2;
            mAh[kt2][half]     = pack_h(h0, h1);
            mAh[kt2][half + 1] = pack_h(h2, h3);
            mAl[kt2][half]     = pack_h(l0, l1);
            mAl[kt2][half + 1] = pack_h(l2, l3);
        }

        // ---- layer 2 + layer 3 fused ----
        float s0 = 0.0f, s8 = 0.0f;
        #pragma unroll
        for (int nt = 0; nt < 4; ++nt) {
            float dd[4] = { bi2[nt][0], bi2[nt][1], bi2[nt][0], bi2[nt][1] };
            #pragma unroll
            for (int kt = 0; kt < 2; ++kt) {
                uint4 B = bf2[nt][kt][lane];
                mma16816(dd, mAh[kt], B.x, B.z);
                mma16816(dd, mAh[kt], B.y, B.w);
                mma16816(dd, mAl[kt], B.x, B.z);
            }
            s0 = fmaf(w3v[nt][0], fmaxf(dd[0], 0.0f), s0);
            s0 = fmaf(w3v[nt][1], fmaxf(dd[1], 0.0f), s0);
            s8 = fmaf(w3v[nt][0], fmaxf(dd[2], 0.0f), s8);
            s8 = fmaf(w3v[nt][1], fmaxf(dd[3], 0.0f), s8);
        }
        // quad butterfly reduce over q (cols)
        s0 += __shfl_xor_sync(0xFFFFFFFF, s0, 1);
        s0 += __shfl_xor_sync(0xFFFFFFFF, s0, 2);
        s8 += __shfl_xor_sync(0xFFFFFFFF, s8, 1);
        s8 += __shfl_xor_sync(0xFFFFFFFF, s8, 2);

        if (q == 0) {
            int b = wid * 128 + mt * 16 + nrow;
            out[b * (S * D) + base_out]       = s0 + b3s;
            out[(b + 8) * (S * D) + base_out] = s8 + b3s;
        }
    }
}

// ---------------- launch ----------------
extern "C" void kernel_launch(void* const* d_in, const int* in_sizes, int n_in,
                              void* d_out, int out_size)
{
    const float* x  = (const float*)d_in[0];
    const float* z  = (const float*)d_in[1];
    const float* W0 = (const float*)d_in[2];
    const float* b0 = (const float*)d_in[3];
    const float* W1 = (const float*)d_in[4];
    const float* b1 = (const float*)d_in[5];
    const float* W2 = (const float*)d_in[6];
    const float* b2 = (const float*)d_in[7];
    const float* W3 = (const float*)d_in[8];
    const float* b3 = (const float*)d_in[9];

    float* out  = (float*)d_out;
    float* adjp = out + OUT_ELEMS;  // tuple output: (out, z_adj)

    zadj_kernel<<<S, 512, 3 * 4096 * sizeof(float)>>>(z, adjp);
    xprep_kernel<<<64, 256>>>(x);

    dim3 grid(D, S);   // (c, s)
    mlp_mma_kernel<<<grid, 128>>>(adjp,
                                  W0, b0, W1, b1, W2, b2, W3, b3,
                                  out);
}